// round 4
// baseline (speedup 1.0000x reference)
#include <cuda_runtime.h>
#include <cuda_bf16.h>
#include <cstdint>

#define NROWS 8192
#define D_IN  64
#define D_OUT 32000
#define MT 128
#define NT 128
#define NBLK   (D_OUT / NT)     // 250 column blocks
#define NBLK2  (NBLK * 2)       // 500: one partial per (row, warp-n-half)
#define MBLK   (NROWS / MT)     // 64

// smem row pitch: 72 bf16 = 144 B = 36 words -> 8 consecutive rows hit
// disjoint bank groups (4*r + w covers 32 banks), conflict-free LDS.
#define PITCH_W 36

// -------------------- device scratch (no allocs allowed) --------------------
__device__ uint32_t g_wt_hi[D_OUT * 32];   // W^T rows: [n][32] u32 = 64 bf16
__device__ uint32_t g_wt_lo[D_OUT * 32];
__device__ float    g_partials[NROWS * NBLK2];  // 16.4 MB
__device__ float    g_rowinv[NROWS];

__device__ __forceinline__ uint32_t pack_bf2(float a, float b) {
    uint32_t lo = __bfloat16_as_ushort(__float2bfloat16_rn(a));
    uint32_t hi = __bfloat16_as_ushort(__float2bfloat16_rn(b));
    return lo | (hi << 16);
}

__device__ __forceinline__ void mma_bf16(float* c, const uint32_t* a, uint32_t b0, uint32_t b1) {
    asm volatile(
        "mma.sync.aligned.m16n8k16.row.col.f32.bf16.bf16.f32 "
        "{%0,%1,%2,%3}, {%4,%5,%6,%7}, {%8,%9}, {%0,%1,%2,%3};"
        : "+f"(c[0]), "+f"(c[1]), "+f"(c[2]), "+f"(c[3])
        : "r"(a[0]), "r"(a[1]), "r"(a[2]), "r"(a[3]), "r"(b0), "r"(b1));
}

// ---------------------------------------------------------------------------
// prep_w: W[64][32000] -> transposed bf16 hi/lo rows [32000][64] (128B each)
// ---------------------------------------------------------------------------
__global__ __launch_bounds__(256) void prep_w_kernel(const float* __restrict__ w) {
    int n = blockIdx.x * 256 + threadIdx.x;
    uint32_t hi[32], lo[32];
#pragma unroll
    for (int j = 0; j < 32; ++j) {
        float v0 = w[(2 * j) * D_OUT + n];
        float v1 = w[(2 * j + 1) * D_OUT + n];
        __nv_bfloat16 h0 = __float2bfloat16_rn(v0);
        __nv_bfloat16 h1 = __float2bfloat16_rn(v1);
        hi[j] = (uint32_t)__bfloat16_as_ushort(h0) | ((uint32_t)__bfloat16_as_ushort(h1) << 16);
        lo[j] = pack_bf2(v0 - __bfloat162float(h0), v1 - __bfloat162float(h1));
    }
    uint4* dh = reinterpret_cast<uint4*>(g_wt_hi) + (size_t)n * 8;
    uint4* dl = reinterpret_cast<uint4*>(g_wt_lo) + (size_t)n * 8;
#pragma unroll
    for (int j = 0; j < 8; ++j) {
        dh[j] = make_uint4(hi[4*j], hi[4*j+1], hi[4*j+2], hi[4*j+3]);
        dl[j] = make_uint4(lo[4*j], lo[4*j+1], lo[4*j+2], lo[4*j+3]);
    }
}

// ---------------------------------------------------------------------------
// Main HMMA pass. do_store=0: accumulate exp-sums into g_partials.
//                 do_store=1: out[row][col] = exp(logit) * g_rowinv[row].
// Grid (NBLK, MBLK), 256 threads, dynamic smem 72KB.
// ---------------------------------------------------------------------------
__global__ __launch_bounds__(256)
void mma_pass_kernel(const float* __restrict__ x, float* __restrict__ out, int do_store) {
    extern __shared__ uint32_t smem[];
    uint32_t* sAhi = smem;                       // [128][36] words
    uint32_t* sAlo = smem + 128 * PITCH_W;
    uint32_t* sBhi = smem + 2 * 128 * PITCH_W;   // W^T: [n][36] words
    uint32_t* sBlo = smem + 3 * 128 * PITCH_W;

    const int tid  = threadIdx.x;
    const int wid  = tid >> 5;
    const int lane = tid & 31;
    const int m0 = blockIdx.y * MT;
    const int n0 = blockIdx.x * NT;

    // ---- load A: 1/x -> bf16 hi/lo. 256 thr: row=tid>>1, half=tid&1 ----
    {
        int row = tid >> 1, half = tid & 1;
        const float4* xr = reinterpret_cast<const float4*>(
            &x[(size_t)(m0 + row) * D_IN + half * 32]);
        uint32_t* dh = &sAhi[row * PITCH_W + half * 16];
        uint32_t* dl = &sAlo[row * PITCH_W + half * 16];
#pragma unroll
        for (int j = 0; j < 8; ++j) {
            float4 v = xr[j];
            float r0 = 1.0f / v.x, r1 = 1.0f / v.y, r2 = 1.0f / v.z, r3 = 1.0f / v.w;
            __nv_bfloat16 h0 = __float2bfloat16_rn(r0), h1 = __float2bfloat16_rn(r1);
            __nv_bfloat16 h2 = __float2bfloat16_rn(r2), h3 = __float2bfloat16_rn(r3);
            uint32_t p0 = (uint32_t)__bfloat16_as_ushort(h0) | ((uint32_t)__bfloat16_as_ushort(h1) << 16);
            uint32_t p1 = (uint32_t)__bfloat16_as_ushort(h2) | ((uint32_t)__bfloat16_as_ushort(h3) << 16);
            dh[2*j]   = p0;
            dh[2*j+1] = p1;
            dl[2*j]   = pack_bf2(r0 - __bfloat162float(h0), r1 - __bfloat162float(h1));
            dl[2*j+1] = pack_bf2(r2 - __bfloat162float(h2), r3 - __bfloat162float(h3));
        }
    }
    // ---- load B^T rows (prepped bf16) ----
    {
        int n = tid >> 1, half = tid & 1;
        const uint4* sh = reinterpret_cast<const uint4*>(g_wt_hi + (size_t)(n0 + n) * 32 + half * 16);
        const uint4* sl = reinterpret_cast<const uint4*>(g_wt_lo + (size_t)(n0 + n) * 32 + half * 16);
        uint4* dh = reinterpret_cast<uint4*>(&sBhi[n * PITCH_W + half * 16]);
        uint4* dl = reinterpret_cast<uint4*>(&sBlo[n * PITCH_W + half * 16]);
#pragma unroll
        for (int q = 0; q < 4; ++q) { dh[q] = sh[q]; dl[q] = sl[q]; }
    }
    __syncthreads();

    // ---- mainloop: 12 HMMA-k-steps (4 kc x 3 compensation terms) ----
    const int wm = wid & 3;    // 0..3: m quarter
    const int wn = wid >> 2;   // 0..1: n half
    const int g  = lane >> 2;  // group row
    const int t  = lane & 3;   // thread-in-group

    float acc[2][8][4];
#pragma unroll
    for (int mi = 0; mi < 2; ++mi)
#pragma unroll
        for (int ni = 0; ni < 8; ++ni)
#pragma unroll
            for (int c = 0; c < 4; ++c) acc[mi][ni][c] = 0.0f;

    const int aRow = wm * 32 + g;          // row for mi=0 (a0/a2); +16 for mi=1
    const int bRow0 = wn * 64 + g;         // n for ni=0; +8 per ni

#pragma unroll
    for (int kc = 0; kc < 4; ++kc) {
        const int wb = kc * 8 + t;         // k word for a0/a1/b0; +4 for a2/a3/b1
        uint32_t ahi[2][4], alo[2][4];
#pragma unroll
        for (int mi = 0; mi < 2; ++mi) {
            int r = (aRow + mi * 16) * PITCH_W;
            ahi[mi][0] = sAhi[r + wb];
            ahi[mi][1] = sAhi[r + 8 * PITCH_W + wb];
            ahi[mi][2] = sAhi[r + wb + 4];
            ahi[mi][3] = sAhi[r + 8 * PITCH_W + wb + 4];
            alo[mi][0] = sAlo[r + wb];
            alo[mi][1] = sAlo[r + 8 * PITCH_W + wb];
            alo[mi][2] = sAlo[r + wb + 4];
            alo[mi][3] = sAlo[r + 8 * PITCH_W + wb + 4];
        }
#pragma unroll
        for (int ni = 0; ni < 8; ++ni) {
            int nb = (bRow0 + ni * 8) * PITCH_W;
            uint32_t b0h = sBhi[nb + wb], b1h = sBhi[nb + wb + 4];
            uint32_t b0l = sBlo[nb + wb], b1l = sBlo[nb + wb + 4];
#pragma unroll
            for (int mi = 0; mi < 2; ++mi) {
                mma_bf16(acc[mi][ni], ahi[mi], b0h, b1h);
                mma_bf16(acc[mi][ni], alo[mi], b0h, b1h);
                mma_bf16(acc[mi][ni], ahi[mi], b0l, b1l);
            }
        }
    }

    // ---- epilogue: exp, then either row-partial-sums or normalized store ----
#pragma unroll
    for (int mi = 0; mi < 2; ++mi) {
        const int rg = m0 + wm * 32 + mi * 16 + g;   // global row (and rg+8)
        if (do_store) {
            const float inv0 = g_rowinv[rg];
            const float inv8 = g_rowinv[rg + 8];
            float* r0p = out + (size_t)rg * D_OUT + n0 + wn * 64 + t * 2;
            float* r8p = r0p + (size_t)8 * D_OUT;
#pragma unroll
            for (int ni = 0; ni < 8; ++ni) {
                float e0 = __expf(acc[mi][ni][0]);
                float e1 = __expf(acc[mi][ni][1]);
                float e2 = __expf(acc[mi][ni][2]);
                float e3 = __expf(acc[mi][ni][3]);
                *reinterpret_cast<float2*>(r0p + ni * 8) = make_float2(e0 * inv0, e1 * inv0);
                *reinterpret_cast<float2*>(r8p + ni * 8) = make_float2(e2 * inv8, e3 * inv8);
            }
        } else {
            float s0 = 0.0f, s8 = 0.0f;
#pragma unroll
            for (int ni = 0; ni < 8; ++ni) {
                s0 += __expf(acc[mi][ni][0]) + __expf(acc[mi][ni][1]);
                s8 += __expf(acc[mi][ni][2]) + __expf(acc[mi][ni][3]);
            }
            s0 += __shfl_xor_sync(0xffffffffu, s0, 1);
            s0 += __shfl_xor_sync(0xffffffffu, s0, 2);
            s8 += __shfl_xor_sync(0xffffffffu, s8, 1);
            s8 += __shfl_xor_sync(0xffffffffu, s8, 2);
            if (t == 0) {
                int pcol = blockIdx.x * 2 + wn;
                g_partials[(size_t)rg * NBLK2 + pcol]       = s0;
                g_partials[(size_t)(rg + 8) * NBLK2 + pcol] = s8;
            }
        }
    }
}

// ---------------------------------------------------------------------------
// rowinv: reduce 500 partials per row -> 1/rowsum. One warp per row.
// ---------------------------------------------------------------------------
__global__ __launch_bounds__(256) void rowinv_kernel() {
    int warp = threadIdx.x >> 5;
    int lane = threadIdx.x & 31;
    int row = blockIdx.x * 8 + warp;
    float s = 0.0f;
    for (int i = lane; i < NBLK2; i += 32) s += g_partials[(size_t)row * NBLK2 + i];
#pragma unroll
    for (int off = 16; off >= 1; off >>= 1)
        s += __shfl_xor_sync(0xffffffffu, s, off);
    if (lane == 0) g_rowinv[row] = 1.0f / s;
}

__global__ void tail_kernel(float* __restrict__ out, long long base, long long n) {
    long long i = (long long)blockIdx.x * 256 + threadIdx.x;
    if (i < n) out[base + i] = 0.0f;
}

extern "C" void kernel_launch(void* const* d_in, const int* in_sizes, int n_in,
                              void* d_out, int out_size) {
    const float* x = (const float*)d_in[0];
    const float* w = (const float*)d_in[1];
    float* out = (float*)d_out;

    const int smem_bytes = 4 * 128 * PITCH_W * 4;   // 73728
    static int attr_set = 0;
    if (!attr_set) {
        cudaFuncSetAttribute(mma_pass_kernel,
                             cudaFuncAttributeMaxDynamicSharedMemorySize, smem_bytes);
        attr_set = 1;
    }

    prep_w_kernel<<<D_OUT / 256, 256>>>(w);

    dim3 grid(NBLK, MBLK);   // (250, 64)
    mma_pass_kernel<<<grid, 256, smem_bytes>>>(x, out, 0);  // pass 1: exp-sums
    rowinv_kernel<<<NROWS / 8, 256>>>();
    mma_pass_kernel<<<grid, 256, smem_bytes>>>(x, out, 1);  // pass 2: normalized store

    long long n_main = (long long)NROWS * D_OUT;
    long long tail = (long long)out_size - n_main;
    if (tail > 0) {
        int blocks = (int)((tail + 255) / 256);
        tail_kernel<<<blocks, 256>>>(out, n_main, tail);
    }
}

// round 5
// speedup vs baseline: 1.0003x; 1.0003x over previous
#include <cuda_runtime.h>
#include <cuda_bf16.h>
#include <cstdint>

#define NROWS 8192
#define D_IN  64
#define D_OUT 32000
#define MT 128
#define NT 128
#define NBLK   (D_OUT / NT)     // 250 column blocks
#define NBLK2  (NBLK * 2)       // 500: one partial per (row, warp-n-half)
#define MBLK   (NROWS / MT)     // 64

// smem row pitch: 72 bf16 = 144 B = 36 words -> 8 consecutive rows hit
// disjoint bank groups (4*r + w covers 32 banks), conflict-free LDS.
#define PITCH_W 36

// -------------------- device scratch (no allocs allowed) --------------------
__device__ uint32_t g_wt_hi[D_OUT * 32];   // W^T rows: [n][32] u32 = 64 bf16
__device__ uint32_t g_wt_lo[D_OUT * 32];
__device__ float    g_partials[NROWS * NBLK2];  // 16.4 MB
__device__ float    g_rowinv[NROWS];

__device__ __forceinline__ uint32_t pack_bf2(float a, float b) {
    uint32_t lo = __bfloat16_as_ushort(__float2bfloat16_rn(a));
    uint32_t hi = __bfloat16_as_ushort(__float2bfloat16_rn(b));
    return lo | (hi << 16);
}

__device__ __forceinline__ void mma_bf16(float* c, const uint32_t* a, uint32_t b0, uint32_t b1) {
    asm volatile(
        "mma.sync.aligned.m16n8k16.row.col.f32.bf16.bf16.f32 "
        "{%0,%1,%2,%3}, {%4,%5,%6,%7}, {%8,%9}, {%0,%1,%2,%3};"
        : "+f"(c[0]), "+f"(c[1]), "+f"(c[2]), "+f"(c[3])
        : "r"(a[0]), "r"(a[1]), "r"(a[2]), "r"(a[3]), "r"(b0), "r"(b1));
}

// ---------------------------------------------------------------------------
// prep_w: W[64][32000] -> transposed bf16 hi/lo rows [32000][64] (128B each)
// ---------------------------------------------------------------------------
__global__ __launch_bounds__(256) void prep_w_kernel(const float* __restrict__ w) {
    int n = blockIdx.x * 256 + threadIdx.x;
    uint32_t hi[32], lo[32];
#pragma unroll
    for (int j = 0; j < 32; ++j) {
        float v0 = w[(2 * j) * D_OUT + n];
        float v1 = w[(2 * j + 1) * D_OUT + n];
        __nv_bfloat16 h0 = __float2bfloat16_rn(v0);
        __nv_bfloat16 h1 = __float2bfloat16_rn(v1);
        hi[j] = (uint32_t)__bfloat16_as_ushort(h0) | ((uint32_t)__bfloat16_as_ushort(h1) << 16);
        lo[j] = pack_bf2(v0 - __bfloat162float(h0), v1 - __bfloat162float(h1));
    }
    uint4* dh = reinterpret_cast<uint4*>(g_wt_hi) + (size_t)n * 8;
    uint4* dl = reinterpret_cast<uint4*>(g_wt_lo) + (size_t)n * 8;
#pragma unroll
    for (int j = 0; j < 8; ++j) {
        dh[j] = make_uint4(hi[4*j], hi[4*j+1], hi[4*j+2], hi[4*j+3]);
        dl[j] = make_uint4(lo[4*j], lo[4*j+1], lo[4*j+2], lo[4*j+3]);
    }
}

// ---------------------------------------------------------------------------
// Main HMMA pass. do_store=0: accumulate exp-sums into g_partials.
//                 do_store=1: out[row][col] = exp(logit) * g_rowinv[row].
// Grid (NBLK, MBLK), 256 threads, dynamic smem 72KB.
// ---------------------------------------------------------------------------
__global__ __launch_bounds__(256)
void mma_pass_kernel(const float* __restrict__ x, float* __restrict__ out, int do_store) {
    extern __shared__ uint32_t smem[];
    uint32_t* sAhi = smem;                       // [128][36] words
    uint32_t* sAlo = smem + 128 * PITCH_W;
    uint32_t* sBhi = smem + 2 * 128 * PITCH_W;   // W^T: [n][36] words
    uint32_t* sBlo = smem + 3 * 128 * PITCH_W;

    const int tid  = threadIdx.x;
    const int wid  = tid >> 5;
    const int lane = tid & 31;
    const int m0 = blockIdx.y * MT;
    const int n0 = blockIdx.x * NT;

    // ---- load A: 1/x -> bf16 hi/lo. 256 thr: row=tid>>1, half=tid&1 ----
    {
        int row = tid >> 1, half = tid & 1;
        const float4* xr = reinterpret_cast<const float4*>(
            &x[(size_t)(m0 + row) * D_IN + half * 32]);
        uint32_t* dh = &sAhi[row * PITCH_W + half * 16];
        uint32_t* dl = &sAlo[row * PITCH_W + half * 16];
#pragma unroll
        for (int j = 0; j < 8; ++j) {
            float4 v = xr[j];
            float r0 = 1.0f / v.x, r1 = 1.0f / v.y, r2 = 1.0f / v.z, r3 = 1.0f / v.w;
            __nv_bfloat16 h0 = __float2bfloat16_rn(r0), h1 = __float2bfloat16_rn(r1);
            __nv_bfloat16 h2 = __float2bfloat16_rn(r2), h3 = __float2bfloat16_rn(r3);
            uint32_t p0 = (uint32_t)__bfloat16_as_ushort(h0) | ((uint32_t)__bfloat16_as_ushort(h1) << 16);
            uint32_t p1 = (uint32_t)__bfloat16_as_ushort(h2) | ((uint32_t)__bfloat16_as_ushort(h3) << 16);
            dh[2*j]   = p0;
            dh[2*j+1] = p1;
            dl[2*j]   = pack_bf2(r0 - __bfloat162float(h0), r1 - __bfloat162float(h1));
            dl[2*j+1] = pack_bf2(r2 - __bfloat162float(h2), r3 - __bfloat162float(h3));
        }
    }
    // ---- load B^T rows (prepped bf16) ----
    {
        int n = tid >> 1, half = tid & 1;
        const uint4* sh = reinterpret_cast<const uint4*>(g_wt_hi + (size_t)(n0 + n) * 32 + half * 16);
        const uint4* sl = reinterpret_cast<const uint4*>(g_wt_lo + (size_t)(n0 + n) * 32 + half * 16);
        uint4* dh = reinterpret_cast<uint4*>(&sBhi[n * PITCH_W + half * 16]);
        uint4* dl = reinterpret_cast<uint4*>(&sBlo[n * PITCH_W + half * 16]);
#pragma unroll
        for (int q = 0; q < 4; ++q) { dh[q] = sh[q]; dl[q] = sl[q]; }
    }
    __syncthreads();

    // ---- mainloop: 12 HMMA-k-steps (4 kc x 3 compensation terms) ----
    const int wm = wid & 3;    // 0..3: m quarter
    const int wn = wid >> 2;   // 0..1: n half
    const int g  = lane >> 2;  // group row
    const int t  = lane & 3;   // thread-in-group

    float acc[2][8][4];
#pragma unroll
    for (int mi = 0; mi < 2; ++mi)
#pragma unroll
        for (int ni = 0; ni < 8; ++ni)
#pragma unroll
            for (int c = 0; c < 4; ++c) acc[mi][ni][c] = 0.0f;

    const int aRow = wm * 32 + g;          // row for mi=0 (a0/a2); +16 for mi=1
    const int bRow0 = wn * 64 + g;         // n for ni=0; +8 per ni

#pragma unroll
    for (int kc = 0; kc < 4; ++kc) {
        const int wb = kc * 8 + t;         // k word for a0/a1/b0; +4 for a2/a3/b1
        uint32_t ahi[2][4], alo[2][4];
#pragma unroll
        for (int mi = 0; mi < 2; ++mi) {
            int r = (aRow + mi * 16) * PITCH_W;
            ahi[mi][0] = sAhi[r + wb];
            ahi[mi][1] = sAhi[r + 8 * PITCH_W + wb];
            ahi[mi][2] = sAhi[r + wb + 4];
            ahi[mi][3] = sAhi[r + 8 * PITCH_W + wb + 4];
            alo[mi][0] = sAlo[r + wb];
            alo[mi][1] = sAlo[r + 8 * PITCH_W + wb];
            alo[mi][2] = sAlo[r + wb + 4];
            alo[mi][3] = sAlo[r + 8 * PITCH_W + wb + 4];
        }
#pragma unroll
        for (int ni = 0; ni < 8; ++ni) {
            int nb = (bRow0 + ni * 8) * PITCH_W;
            uint32_t b0h = sBhi[nb + wb], b1h = sBhi[nb + wb + 4];
            uint32_t b0l = sBlo[nb + wb], b1l = sBlo[nb + wb + 4];
#pragma unroll
            for (int mi = 0; mi < 2; ++mi) {
                mma_bf16(acc[mi][ni], ahi[mi], b0h, b1h);
                mma_bf16(acc[mi][ni], alo[mi], b0h, b1h);
                mma_bf16(acc[mi][ni], ahi[mi], b0l, b1l);
            }
        }
    }

    // ---- epilogue: exp, then either row-partial-sums or normalized store ----
#pragma unroll
    for (int mi = 0; mi < 2; ++mi) {
        const int rg = m0 + wm * 32 + mi * 16 + g;   // global row (and rg+8)
        if (do_store) {
            const float inv0 = g_rowinv[rg];
            const float inv8 = g_rowinv[rg + 8];
            float* r0p = out + (size_t)rg * D_OUT + n0 + wn * 64 + t * 2;
            float* r8p = r0p + (size_t)8 * D_OUT;
#pragma unroll
            for (int ni = 0; ni < 8; ++ni) {
                float e0 = __expf(acc[mi][ni][0]);
                float e1 = __expf(acc[mi][ni][1]);
                float e2 = __expf(acc[mi][ni][2]);
                float e3 = __expf(acc[mi][ni][3]);
                *reinterpret_cast<float2*>(r0p + ni * 8) = make_float2(e0 * inv0, e1 * inv0);
                *reinterpret_cast<float2*>(r8p + ni * 8) = make_float2(e2 * inv8, e3 * inv8);
            }
        } else {
            float s0 = 0.0f, s8 = 0.0f;
#pragma unroll
            for (int ni = 0; ni < 8; ++ni) {
                s0 += __expf(acc[mi][ni][0]) + __expf(acc[mi][ni][1]);
                s8 += __expf(acc[mi][ni][2]) + __expf(acc[mi][ni][3]);
            }
            s0 += __shfl_xor_sync(0xffffffffu, s0, 1);
            s0 += __shfl_xor_sync(0xffffffffu, s0, 2);
            s8 += __shfl_xor_sync(0xffffffffu, s8, 1);
            s8 += __shfl_xor_sync(0xffffffffu, s8, 2);
            if (t == 0) {
                int pcol = blockIdx.x * 2 + wn;
                g_partials[(size_t)rg * NBLK2 + pcol]       = s0;
                g_partials[(size_t)(rg + 8) * NBLK2 + pcol] = s8;
            }
        }
    }
}

// ---------------------------------------------------------------------------
// rowinv: reduce 500 partials per row -> 1/rowsum. One warp per row.
// ---------------------------------------------------------------------------
__global__ __launch_bounds__(256) void rowinv_kernel() {
    int warp = threadIdx.x >> 5;
    int lane = threadIdx.x & 31;
    int row = blockIdx.x * 8 + warp;
    float s = 0.0f;
    for (int i = lane; i < NBLK2; i += 32) s += g_partials[(size_t)row * NBLK2 + i];
#pragma unroll
    for (int off = 16; off >= 1; off >>= 1)
        s += __shfl_xor_sync(0xffffffffu, s, off);
    if (lane == 0) g_rowinv[row] = 1.0f / s;
}

__global__ void tail_kernel(float* __restrict__ out, long long base, long long n) {
    long long i = (long long)blockIdx.x * 256 + threadIdx.x;
    if (i < n) out[base + i] = 0.0f;
}

extern "C" void kernel_launch(void* const* d_in, const int* in_sizes, int n_in,
                              void* d_out, int out_size) {
    const float* x = (const float*)d_in[0];
    const float* w = (const float*)d_in[1];
    float* out = (float*)d_out;

    const int smem_bytes = 4 * 128 * PITCH_W * 4;   // 73728
    static int attr_set = 0;
    if (!attr_set) {
        cudaFuncSetAttribute(mma_pass_kernel,
                             cudaFuncAttributeMaxDynamicSharedMemorySize, smem_bytes);
        attr_set = 1;
    }

    prep_w_kernel<<<D_OUT / 256, 256>>>(w);

    dim3 grid(NBLK, MBLK);   // (250, 64)
    mma_pass_kernel<<<grid, 256, smem_bytes>>>(x, out, 0);  // pass 1: exp-sums
    rowinv_kernel<<<NROWS / 8, 256>>>();
    mma_pass_kernel<<<grid, 256, smem_bytes>>>(x, out, 1);  // pass 2: normalized store

    long long n_main = (long long)NROWS * D_OUT;
    long long tail = (long long)out_size - n_main;
    if (tail > 0) {
        int blocks = (int)((tail + 255) / 256);
        tail_kernel<<<blocks, 256>>>(out, n_main, tail);
    }
}

// round 7
// speedup vs baseline: 1.5068x; 1.5065x over previous
#include <cuda_runtime.h>
#include <cuda_bf16.h>
#include <cstdint>

#define NROWS 8192
#define D_IN  64
#define D_OUT 32000
#define MT 128
#define NT 128
#define NBLK   (D_OUT / NT)     // 250
#define NBLK2  (NBLK * 2)       // 500 partials per row
#define MBLK   (NROWS / MT)     // 64

// smem row: [32 words hi | 32 words lo | 4 words pad] = 68 words = 272B.
// 272B pitch -> row r starts at bank 4r mod 32: any 8 consecutive rows
// hit disjoint 16B bank groups => every ldmatrix phase conflict-free.
#define PITCH 68

// -------------------- device scratch --------------------
__device__ uint32_t g_wprep[D_OUT * 64];   // [n][ hi0..31 | lo0..31 ] bf16x2 words
__device__ uint32_t g_xprep[NROWS * 64];   // [row][ hi | lo ] of 1/x
__device__ float    g_partials[NROWS * NBLK2];
__device__ float    g_rowinv[NROWS];

__device__ __forceinline__ uint32_t pack_bf2(float a, float b) {
    uint32_t lo = __bfloat16_as_ushort(__float2bfloat16_rn(a));
    uint32_t hi = __bfloat16_as_ushort(__float2bfloat16_rn(b));
    return lo | (hi << 16);
}

__device__ __forceinline__ uint32_t smem_u32(const void* p) {
    uint32_t a;
    asm("{ .reg .u64 t; cvta.to.shared.u64 t, %1; cvt.u32.u64 %0, t; }" : "=r"(a) : "l"(p));
    return a;
}

__device__ __forceinline__ void cpa16(uint32_t s, const void* g) {
    asm volatile("cp.async.cg.shared.global [%0], [%1], 16;" :: "r"(s), "l"(g));
}

__device__ __forceinline__ void ldsm4(uint32_t* r, uint32_t a) {
    asm volatile("ldmatrix.sync.aligned.m8n8.x4.shared.b16 {%0,%1,%2,%3}, [%4];"
                 : "=r"(r[0]), "=r"(r[1]), "=r"(r[2]), "=r"(r[3]) : "r"(a));
}

__device__ __forceinline__ void mma_bf16(float* c, const uint32_t* a, uint32_t b0, uint32_t b1) {
    asm volatile(
        "mma.sync.aligned.m16n8k16.row.col.f32.bf16.bf16.f32 "
        "{%0,%1,%2,%3}, {%4,%5,%6,%7}, {%8,%9}, {%0,%1,%2,%3};"
        : "+f"(c[0]), "+f"(c[1]), "+f"(c[2]), "+f"(c[3])
        : "r"(a[0]), "r"(a[1]), "r"(a[2]), "r"(a[3]), "r"(b0), "r"(b1));
}

// ---------------------------------------------------------------------------
// prep_w: W[64][32000] -> rows [n][hi32|lo32]
// ---------------------------------------------------------------------------
__global__ __launch_bounds__(256) void prep_w_kernel(const float* __restrict__ w) {
    int n = blockIdx.x * 256 + threadIdx.x;
    uint32_t hi[32], lo[32];
#pragma unroll
    for (int j = 0; j < 32; ++j) {
        float v0 = w[(2 * j) * D_OUT + n];
        float v1 = w[(2 * j + 1) * D_OUT + n];
        __nv_bfloat16 h0 = __float2bfloat16_rn(v0);
        __nv_bfloat16 h1 = __float2bfloat16_rn(v1);
        hi[j] = (uint32_t)__bfloat16_as_ushort(h0) | ((uint32_t)__bfloat16_as_ushort(h1) << 16);
        lo[j] = pack_bf2(v0 - __bfloat162float(h0), v1 - __bfloat162float(h1));
    }
    uint4* d = reinterpret_cast<uint4*>(g_wprep) + (size_t)n * 16;
#pragma unroll
    for (int j = 0; j < 8; ++j) {
        d[j]     = make_uint4(hi[4*j], hi[4*j+1], hi[4*j+2], hi[4*j+3]);
        d[j + 8] = make_uint4(lo[4*j], lo[4*j+1], lo[4*j+2], lo[4*j+3]);
    }
}

// ---------------------------------------------------------------------------
// prep_x: x[8192][64] -> rows [r][hi32|lo32] of 1/x. 2 threads per row.
// ---------------------------------------------------------------------------
__global__ __launch_bounds__(256) void prep_x_kernel(const float* __restrict__ x) {
    int tid = blockIdx.x * 256 + threadIdx.x;
    int row = tid >> 1, half = tid & 1;
    const float4* xr = reinterpret_cast<const float4*>(&x[(size_t)row * D_IN + half * 32]);
    uint32_t hi[16], lo[16];
#pragma unroll
    for (int j = 0; j < 8; ++j) {
        float4 v = xr[j];
        float r0 = 1.0f / v.x, r1 = 1.0f / v.y, r2 = 1.0f / v.z, r3 = 1.0f / v.w;
        __nv_bfloat16 h0 = __float2bfloat16_rn(r0), h1 = __float2bfloat16_rn(r1);
        __nv_bfloat16 h2 = __float2bfloat16_rn(r2), h3 = __float2bfloat16_rn(r3);
        hi[2*j]   = (uint32_t)__bfloat16_as_ushort(h0) | ((uint32_t)__bfloat16_as_ushort(h1) << 16);
        hi[2*j+1] = (uint32_t)__bfloat16_as_ushort(h2) | ((uint32_t)__bfloat16_as_ushort(h3) << 16);
        lo[2*j]   = pack_bf2(r0 - __bfloat162float(h0), r1 - __bfloat162float(h1));
        lo[2*j+1] = pack_bf2(r2 - __bfloat162float(h2), r3 - __bfloat162float(h3));
    }
    uint4* d = reinterpret_cast<uint4*>(g_xprep) + (size_t)row * 16 + half * 4;
#pragma unroll
    for (int j = 0; j < 4; ++j) {
        d[j]     = make_uint4(hi[4*j], hi[4*j+1], hi[4*j+2], hi[4*j+3]);
        d[j + 8] = make_uint4(lo[4*j], lo[4*j+1], lo[4*j+2], lo[4*j+3]);
    }
}

// ---------------------------------------------------------------------------
// Main HMMA pass (ldmatrix operand path).
// do_store=0: exp-sums into g_partials. do_store=1: normalized store.
// ---------------------------------------------------------------------------
__global__ __launch_bounds__(256)
void mma_pass_kernel(float* __restrict__ out, int do_store) {
    extern __shared__ uint32_t smem[];
    uint32_t* sA = smem;                 // [128][68]
    uint32_t* sB = smem + 128 * PITCH;   // [128][68]

    const int tid  = threadIdx.x;
    const int wid  = tid >> 5;
    const int lane = tid & 31;
    const int m0 = blockIdx.y * MT;
    const int n0 = blockIdx.x * NT;

    const uint32_t sA_a = smem_u32(sA);
    const uint32_t sB_a = smem_u32(sB);

    // ---- prologue: cp.async copy of prepped tiles ----
    // Each tile = 128 rows x 16 uint4 = 2048 uint4. 256 threads x 8 iters.
    {
        const uint4* gA = reinterpret_cast<const uint4*>(g_xprep + (size_t)m0 * 64);
        const uint4* gB = reinterpret_cast<const uint4*>(g_wprep + (size_t)n0 * 64);
#pragma unroll
        for (int j = 0; j < 8; ++j) {
            int f = tid + 256 * j;            // uint4 index: row = f>>4, chunk = f&15
            uint32_t doff = ((f >> 4) * PITCH + (f & 15) * 4) * 4;  // bytes
            cpa16(sA_a + doff, gA + f);
            cpa16(sB_a + doff, gB + f);
        }
        asm volatile("cp.async.commit_group;" ::: "memory");
        asm volatile("cp.async.wait_group 0;" ::: "memory");
    }
    __syncthreads();

    // ---- fragment base addresses (per-lane, ldmatrix) ----
    const int wm = wid & 3;    // m quarter
    const int wn = wid >> 2;   // n half
    const int g  = lane >> 2;
    const int t  = lane & 3;

    // A x4: matrices {rows g k-lo, rows g+8 k-lo, rows g k-hi, rows g+8 k-hi}
    uint32_t aBase[2];
    {
        int arow = lane & 15;
        int ako  = (lane >> 4) * 16;
#pragma unroll
        for (int mi = 0; mi < 2; ++mi)
            aBase[mi] = sA_a + (uint32_t)(wm * 32 + mi * 16 + arow) * 272u + ako;
    }
    // B x4: matrices {b0h, b1h, b0l, b1l}
    uint32_t bBase[8];
    {
        int brow = lane & 7;
        int bko  = ((lane >> 3) & 1) * 16;
        int breg = ((lane >> 4) & 1) * 128;
        uint32_t laneoff = (uint32_t)brow * 272u + bko + breg;
#pragma unroll
        for (int ni = 0; ni < 8; ++ni)
            bBase[ni] = sB_a + (uint32_t)(wn * 64 + ni * 8) * 272u + laneoff;
    }

    float acc[2][8][4];
#pragma unroll
    for (int mi = 0; mi < 2; ++mi)
#pragma unroll
        for (int ni = 0; ni < 8; ++ni)
#pragma unroll
            for (int c = 0; c < 4; ++c) acc[mi][ni][c] = 0.0f;

    // ---- mainloop: 4 k-chunks x (4 A-LDSM + 8 B-LDSM + 48 HMMA) ----
#pragma unroll
    for (int kc = 0; kc < 4; ++kc) {
        const uint32_t ko = kc * 32u;
        uint32_t ah[2][4], al[2][4];
#pragma unroll
        for (int mi = 0; mi < 2; ++mi) {
            ldsm4(ah[mi], aBase[mi] + ko);          // hi words
            ldsm4(al[mi], aBase[mi] + 128u + ko);   // lo words
        }
#pragma unroll
        for (int ni = 0; ni < 8; ++ni) {
            uint32_t b[4];                           // b0h,b1h,b0l,b1l
            ldsm4(b, bBase[ni] + ko);
#pragma unroll
            for (int mi = 0; mi < 2; ++mi) {
                mma_bf16(acc[mi][ni], ah[mi], b[0], b[1]);
                mma_bf16(acc[mi][ni], al[mi], b[0], b[1]);
                mma_bf16(acc[mi][ni], ah[mi], b[2], b[3]);
            }
        }
    }

    // ---- epilogue ----
#pragma unroll
    for (int mi = 0; mi < 2; ++mi) {
        const int rg = m0 + wm * 32 + mi * 16 + g;   // global row (and rg+8)
        if (do_store) {
            const float inv0 = g_rowinv[rg];
            const float inv8 = g_rowinv[rg + 8];
            float* r0p = out + (size_t)rg * D_OUT + n0 + wn * 64 + t * 2;
            float* r8p = r0p + (size_t)8 * D_OUT;
#pragma unroll
            for (int ni = 0; ni < 8; ++ni) {
                float e0 = __expf(acc[mi][ni][0]);
                float e1 = __expf(acc[mi][ni][1]);
                float e2 = __expf(acc[mi][ni][2]);
                float e3 = __expf(acc[mi][ni][3]);
                *reinterpret_cast<float2*>(r0p + ni * 8) = make_float2(e0 * inv0, e1 * inv0);
                *reinterpret_cast<float2*>(r8p + ni * 8) = make_float2(e2 * inv8, e3 * inv8);
            }
        } else {
            float s0 = 0.0f, s8 = 0.0f;
#pragma unroll
            for (int ni = 0; ni < 8; ++ni) {
                s0 += __expf(acc[mi][ni][0]) + __expf(acc[mi][ni][1]);
                s8 += __expf(acc[mi][ni][2]) + __expf(acc[mi][ni][3]);
            }
            s0 += __shfl_xor_sync(0xffffffffu, s0, 1);
            s0 += __shfl_xor_sync(0xffffffffu, s0, 2);
            s8 += __shfl_xor_sync(0xffffffffu, s8, 1);
            s8 += __shfl_xor_sync(0xffffffffu, s8, 2);
            if (t == 0) {
                int pcol = blockIdx.x * 2 + wn;
                g_partials[(size_t)rg * NBLK2 + pcol]       = s0;
                g_partials[(size_t)(rg + 8) * NBLK2 + pcol] = s8;
            }
        }
    }
}

// ---------------------------------------------------------------------------
__global__ __launch_bounds__(256) void rowinv_kernel() {
    int warp = threadIdx.x >> 5;
    int lane = threadIdx.x & 31;
    int row = blockIdx.x * 8 + warp;
    float s = 0.0f;
    for (int i = lane; i < NBLK2; i += 32) s += g_partials[(size_t)row * NBLK2 + i];
#pragma unroll
    for (int off = 16; off >= 1; off >>= 1)
        s += __shfl_xor_sync(0xffffffffu, s, off);
    if (lane == 0) g_rowinv[row] = 1.0f / s;
}

__global__ void tail_kernel(float* __restrict__ out, long long base, long long n) {
    long long i = (long long)blockIdx.x * 256 + threadIdx.x;
    if (i < n) out[base + i] = 0.0f;
}

extern "C" void kernel_launch(void* const* d_in, const int* in_sizes, int n_in,
                              void* d_out, int out_size) {
    const float* x = (const float*)d_in[0];
    const float* w = (const float*)d_in[1];
    float* out = (float*)d_out;

    const int smem_bytes = 2 * 128 * PITCH * 4;   // 69632
    static int attr_set = 0;
    if (!attr_set) {
        cudaFuncSetAttribute(mma_pass_kernel,
                             cudaFuncAttributeMaxDynamicSharedMemorySize, smem_bytes);
        attr_set = 1;
    }

    prep_w_kernel<<<D_OUT / 256, 256>>>(w);
    prep_x_kernel<<<NROWS * 2 / 256, 256>>>(x);

    dim3 grid(NBLK, MBLK);   // (250, 64)
    mma_pass_kernel<<<grid, 256, smem_bytes>>>(out, 0);
    rowinv_kernel<<<NROWS / 8, 256>>>();
    mma_pass_kernel<<<grid, 256, smem_bytes>>>(out, 1);

    long long n_main = (long long)NROWS * D_OUT;
    long long tail = (long long)out_size - n_main;
    if (tail > 0) {
        int blocks = (int)((tail + 255) / 256);
        tail_kernel<<<blocks, 256>>>(out, n_main, tail);
    }
}

// round 8
// speedup vs baseline: 2.0002x; 1.3274x over previous
#include <cuda_runtime.h>
#include <cuda_fp16.h>
#include <cstdint>

#define NROWS 8192
#define D_IN  64
#define D_OUT 32000
#define MT 128
#define NT 128
#define NBLK   (D_OUT / NT)     // 250
#define NBLK2  (NBLK * 2)       // 500 partials per row
#define MBLK   (NROWS / MT)     // 64

// A smem row: 32 words fp16(1/x) + 4 pad = 36 words (144B).
// B smem row: 32 words hi | 32 words lo | 4 pad = 68 words (272B).
// Both pitches are 4 words mod 32 -> 8 consecutive rows hit disjoint 16B
// bank groups => every ldmatrix phase conflict-free.
#define PITCH_A 36
#define PITCH_B 68
#define LOG2E 1.4426950408889634f

// -------------------- device scratch --------------------
__device__ uint32_t g_wprep[D_OUT * 64];   // [n][ hi0..31 | lo0..31 ] f16x2 (W*log2e)
__device__ uint32_t g_xprep[NROWS * 32];   // [row][32] f16x2 of 1/x
__device__ float    g_partials[NROWS * NBLK2];
__device__ float    g_rowinv[NROWS];

__device__ __forceinline__ uint32_t pack_h2(float a, float b) {
    uint32_t lo = __half_as_ushort(__float2half_rn(a));
    uint32_t hi = __half_as_ushort(__float2half_rn(b));
    return lo | (hi << 16);
}

__device__ __forceinline__ uint32_t smem_u32(const void* p) {
    uint32_t a;
    asm("{ .reg .u64 t; cvta.to.shared.u64 t, %1; cvt.u32.u64 %0, t; }" : "=r"(a) : "l"(p));
    return a;
}

__device__ __forceinline__ void cpa16(uint32_t s, const void* g) {
    asm volatile("cp.async.cg.shared.global [%0], [%1], 16;" :: "r"(s), "l"(g));
}

__device__ __forceinline__ void ldsm4(uint32_t* r, uint32_t a) {
    asm volatile("ldmatrix.sync.aligned.m8n8.x4.shared.b16 {%0,%1,%2,%3}, [%4];"
                 : "=r"(r[0]), "=r"(r[1]), "=r"(r[2]), "=r"(r[3]) : "r"(a));
}

__device__ __forceinline__ void mma_f16(float* c, const uint32_t* a, uint32_t b0, uint32_t b1) {
    asm volatile(
        "mma.sync.aligned.m16n8k16.row.col.f32.f16.f16.f32 "
        "{%0,%1,%2,%3}, {%4,%5,%6,%7}, {%8,%9}, {%0,%1,%2,%3};"
        : "+f"(c[0]), "+f"(c[1]), "+f"(c[2]), "+f"(c[3])
        : "r"(a[0]), "r"(a[1]), "r"(a[2]), "r"(a[3]), "r"(b0), "r"(b1));
}

__device__ __forceinline__ float ex2(float x) {
    float y;
    asm("ex2.approx.f32 %0, %1;" : "=f"(y) : "f"(x));
    return y;
}

// ---------------------------------------------------------------------------
// prep_w: W[64][32000] * log2e -> rows [n][hi32|lo32] fp16
// ---------------------------------------------------------------------------
__global__ __launch_bounds__(256) void prep_w_kernel(const float* __restrict__ w) {
    int n = blockIdx.x * 256 + threadIdx.x;
    uint32_t hi[32], lo[32];
#pragma unroll
    for (int j = 0; j < 32; ++j) {
        float v0 = w[(2 * j) * D_OUT + n] * LOG2E;
        float v1 = w[(2 * j + 1) * D_OUT + n] * LOG2E;
        __half h0 = __float2half_rn(v0);
        __half h1 = __float2half_rn(v1);
        hi[j] = (uint32_t)__half_as_ushort(h0) | ((uint32_t)__half_as_ushort(h1) << 16);
        lo[j] = pack_h2(v0 - __half2float(h0), v1 - __half2float(h1));
    }
    uint4* d = reinterpret_cast<uint4*>(g_wprep) + (size_t)n * 16;
#pragma unroll
    for (int j = 0; j < 8; ++j) {
        d[j]     = make_uint4(hi[4*j], hi[4*j+1], hi[4*j+2], hi[4*j+3]);
        d[j + 8] = make_uint4(lo[4*j], lo[4*j+1], lo[4*j+2], lo[4*j+3]);
    }
}

// ---------------------------------------------------------------------------
// prep_x: x[8192][64] -> rows [r][32 words] fp16(1/x). 2 threads per row.
// ---------------------------------------------------------------------------
__global__ __launch_bounds__(256) void prep_x_kernel(const float* __restrict__ x) {
    int tid = blockIdx.x * 256 + threadIdx.x;
    int row = tid >> 1, half = tid & 1;
    const float4* xr = reinterpret_cast<const float4*>(&x[(size_t)row * D_IN + half * 32]);
    uint32_t hi[16];
#pragma unroll
    for (int j = 0; j < 8; ++j) {
        float4 v = xr[j];
        hi[2*j]   = pack_h2(1.0f / v.x, 1.0f / v.y);
        hi[2*j+1] = pack_h2(1.0f / v.z, 1.0f / v.w);
    }
    uint4* d = reinterpret_cast<uint4*>(g_xprep) + (size_t)row * 8 + half * 4;
#pragma unroll
    for (int j = 0; j < 4; ++j)
        d[j] = make_uint4(hi[4*j], hi[4*j+1], hi[4*j+2], hi[4*j+3]);
}

// ---------------------------------------------------------------------------
// Main HMMA pass. do_store=0: exp-sums into g_partials.
//                 do_store=1: out = 2^logit2 * rowinv (logits in log2 domain).
// ---------------------------------------------------------------------------
__global__ __launch_bounds__(256)
void mma_pass_kernel(float* __restrict__ out, int do_store) {
    extern __shared__ uint32_t smem[];
    uint32_t* sA = smem;                   // [128][36]
    uint32_t* sB = smem + 128 * PITCH_A;   // [128][68]

    const int tid  = threadIdx.x;
    const int wid  = tid >> 5;
    const int lane = tid & 31;
    const int m0 = blockIdx.y * MT;
    const int n0 = blockIdx.x * NT;

    const uint32_t sA_a = smem_u32(sA);
    const uint32_t sB_a = smem_u32(sB);

    // ---- prologue: cp.async of prepped tiles ----
    // A tile = 128 rows x 8 uint4 = 1024 uint4 (4/thread).
    // B tile = 128 rows x 16 uint4 = 2048 uint4 (8/thread).
    {
        const uint4* gA = reinterpret_cast<const uint4*>(g_xprep + (size_t)m0 * 32);
        const uint4* gB = reinterpret_cast<const uint4*>(g_wprep + (size_t)n0 * 64);
#pragma unroll
        for (int j = 0; j < 4; ++j) {
            int f = tid + 256 * j;                               // 0..1023
            uint32_t doff = ((f >> 3) * PITCH_A + (f & 7) * 4) * 4;
            cpa16(sA_a + doff, gA + f);
        }
#pragma unroll
        for (int j = 0; j < 8; ++j) {
            int f = tid + 256 * j;                               // 0..2047
            uint32_t doff = ((f >> 4) * PITCH_B + (f & 15) * 4) * 4;
            cpa16(sB_a + doff, gB + f);
        }
        asm volatile("cp.async.commit_group;" ::: "memory");
        asm volatile("cp.async.wait_group 0;" ::: "memory");
    }
    __syncthreads();

    // ---- fragment base addresses ----
    const int wm = wid & 3;
    const int wn = wid >> 2;
    const int g  = lane >> 2;
    const int t  = lane & 3;

    // A x4: {rows g k-lo, rows g+8 k-lo, rows g k-hi, rows g+8 k-hi}
    uint32_t aBase[2];
    {
        int arow = lane & 15;
        int ako  = (lane >> 4) * 16;
#pragma unroll
        for (int mi = 0; mi < 2; ++mi)
            aBase[mi] = sA_a + (uint32_t)(wm * 32 + mi * 16 + arow) * (PITCH_A * 4u) + ako;
    }
    // B x4: {b0h, b1h, b0l, b1l} (lanes 16-31 target the lo region at +128B)
    uint32_t bBase[8];
    {
        int brow = lane & 7;
        int bko  = ((lane >> 3) & 1) * 16;
        int breg = ((lane >> 4) & 1) * 128;
        uint32_t laneoff = (uint32_t)brow * (PITCH_B * 4u) + bko + breg;
#pragma unroll
        for (int ni = 0; ni < 8; ++ni)
            bBase[ni] = sB_a + (uint32_t)(wn * 64 + ni * 8) * (PITCH_B * 4u) + laneoff;
    }

    float acc[2][8][4];
#pragma unroll
    for (int mi = 0; mi < 2; ++mi)
#pragma unroll
        for (int ni = 0; ni < 8; ++ni)
#pragma unroll
            for (int c = 0; c < 4; ++c) acc[mi][ni][c] = 0.0f;

    // ---- mainloop: 4 k-chunks x (2 A-LDSM + 8 B-LDSM + 32 HMMA) ----
#pragma unroll
    for (int kc = 0; kc < 4; ++kc) {
        const uint32_t ko = kc * 32u;
        uint32_t ah[2][4];
#pragma unroll
        for (int mi = 0; mi < 2; ++mi)
            ldsm4(ah[mi], aBase[mi] + ko);
#pragma unroll
        for (int ni = 0; ni < 8; ++ni) {
            uint32_t b[4];                 // b0h,b1h,b0l,b1l
            ldsm4(b, bBase[ni] + ko);
#pragma unroll
            for (int mi = 0; mi < 2; ++mi) {
                mma_f16(acc[mi][ni], ah[mi], b[0], b[1]);
                mma_f16(acc[mi][ni], ah[mi], b[2], b[3]);
            }
        }
    }

    // ---- epilogue (logits are base-2) ----
#pragma unroll
    for (int mi = 0; mi < 2; ++mi) {
        const int rg = m0 + wm * 32 + mi * 16 + g;
        if (do_store) {
            const float inv0 = g_rowinv[rg];
            const float inv8 = g_rowinv[rg + 8];
            float* r0p = out + (size_t)rg * D_OUT + n0 + wn * 64 + t * 2;
            float* r8p = r0p + (size_t)8 * D_OUT;
#pragma unroll
            for (int ni = 0; ni < 8; ++ni) {
                float e0 = ex2(acc[mi][ni][0]);
                float e1 = ex2(acc[mi][ni][1]);
                float e2 = ex2(acc[mi][ni][2]);
                float e3 = ex2(acc[mi][ni][3]);
                __stcs(reinterpret_cast<float2*>(r0p + ni * 8), make_float2(e0 * inv0, e1 * inv0));
                __stcs(reinterpret_cast<float2*>(r8p + ni * 8), make_float2(e2 * inv8, e3 * inv8));
            }
        } else {
            float s0 = 0.0f, s8 = 0.0f;
#pragma unroll
            for (int ni = 0; ni < 8; ++ni) {
                s0 += ex2(acc[mi][ni][0]) + ex2(acc[mi][ni][1]);
                s8 += ex2(acc[mi][ni][2]) + ex2(acc[mi][ni][3]);
            }
            s0 += __shfl_xor_sync(0xffffffffu, s0, 1);
            s0 += __shfl_xor_sync(0xffffffffu, s0, 2);
            s8 += __shfl_xor_sync(0xffffffffu, s8, 1);
            s8 += __shfl_xor_sync(0xffffffffu, s8, 2);
            if (t == 0) {
                int pcol = blockIdx.x * 2 + wn;
                g_partials[(size_t)rg * NBLK2 + pcol]       = s0;
                g_partials[(size_t)(rg + 8) * NBLK2 + pcol] = s8;
            }
        }
    }
}

// ---------------------------------------------------------------------------
__global__ __launch_bounds__(256) void rowinv_kernel() {
    int warp = threadIdx.x >> 5;
    int lane = threadIdx.x & 31;
    int row = blockIdx.x * 8 + warp;
    float s = 0.0f;
    for (int i = lane; i < NBLK2; i += 32) s += g_partials[(size_t)row * NBLK2 + i];
#pragma unroll
    for (int off = 16; off >= 1; off >>= 1)
        s += __shfl_xor_sync(0xffffffffu, s, off);
    if (lane == 0) g_rowinv[row] = 1.0f / s;
}

__global__ void tail_kernel(float* __restrict__ out, long long base, long long n) {
    long long i = (long long)blockIdx.x * 256 + threadIdx.x;
    if (i < n) out[base + i] = 0.0f;
}

extern "C" void kernel_launch(void* const* d_in, const int* in_sizes, int n_in,
                              void* d_out, int out_size) {
    const float* x = (const float*)d_in[0];
    const float* w = (const float*)d_in[1];
    float* out = (float*)d_out;

    const int smem_bytes = (128 * PITCH_A + 128 * PITCH_B) * 4;   // 53248
    static int attr_set = 0;
    if (!attr_set) {
        cudaFuncSetAttribute(mma_pass_kernel,
                             cudaFuncAttributeMaxDynamicSharedMemorySize, smem_bytes);
        attr_set = 1;
    }

    prep_w_kernel<<<D_OUT / 256, 256>>>(w);
    prep_x_kernel<<<NROWS * 2 / 256, 256>>>(x);

    dim3 grid(NBLK, MBLK);   // (250, 64)
    mma_pass_kernel<<<grid, 256, smem_bytes>>>(out, 0);
    rowinv_kernel<<<NROWS / 8, 256>>>();
    mma_pass_kernel<<<grid, 256, smem_bytes>>>(out, 1);

    long long n_main = (long long)NROWS * D_OUT;
    long long tail = (long long)out_size - n_main;
    if (tail > 0) {
        int blocks = (int)((tail + 255) / 256);
        tail_kernel<<<blocks, 256>>>(out, n_main, tail);
    }
}

// round 9
// speedup vs baseline: 2.4349x; 1.2173x over previous
#include <cuda_runtime.h>
#include <cuda_fp16.h>
#include <cstdint>

#define NROWS 8192
#define D_IN  64
#define D_OUT 32000
#define MT 128
#define NT 128
#define NBLK   (D_OUT / NT)     // 250
#define NBLK2  (NBLK * 2)       // 500 partials per row
#define MBLK   (NROWS / MT)     // 64

// smem rows: 32 words fp16 + 4 pad = 36 words (144B).
// 144B pitch -> 8 consecutive rows start at distinct 16B bank groups:
// every ldmatrix phase conflict-free.
#define PITCH 36
#define LOG2E 1.4426950408889634f

// -------------------- device scratch --------------------
__device__ uint32_t g_wprep[D_OUT * 32];   // [n][32] f16x2 of W^T * log2e
__device__ uint32_t g_xprep[NROWS * 32];   // [row][32] f16x2 of 1/x
__device__ float    g_partials[NROWS * NBLK2];
__device__ float    g_rowinv[NROWS];

__device__ __forceinline__ uint32_t pack_h2(float a, float b) {
    uint32_t lo = __half_as_ushort(__float2half_rn(a));
    uint32_t hi = __half_as_ushort(__float2half_rn(b));
    return lo | (hi << 16);
}

__device__ __forceinline__ uint32_t smem_u32(const void* p) {
    uint32_t a;
    asm("{ .reg .u64 t; cvta.to.shared.u64 t, %1; cvt.u32.u64 %0, t; }" : "=r"(a) : "l"(p));
    return a;
}

__device__ __forceinline__ void cpa16(uint32_t s, const void* g) {
    asm volatile("cp.async.cg.shared.global [%0], [%1], 16;" :: "r"(s), "l"(g));
}

__device__ __forceinline__ void ldsm4(uint32_t* r, uint32_t a) {
    asm volatile("ldmatrix.sync.aligned.m8n8.x4.shared.b16 {%0,%1,%2,%3}, [%4];"
                 : "=r"(r[0]), "=r"(r[1]), "=r"(r[2]), "=r"(r[3]) : "r"(a));
}

__device__ __forceinline__ void mma_f16(float* c, const uint32_t* a, uint32_t b0, uint32_t b1) {
    asm volatile(
        "mma.sync.aligned.m16n8k16.row.col.f32.f16.f16.f32 "
        "{%0,%1,%2,%3}, {%4,%5,%6,%7}, {%8,%9}, {%0,%1,%2,%3};"
        : "+f"(c[0]), "+f"(c[1]), "+f"(c[2]), "+f"(c[3])
        : "r"(a[0]), "r"(a[1]), "r"(a[2]), "r"(a[3]), "r"(b0), "r"(b1));
}

__device__ __forceinline__ float ex2(float x) {
    float y;
    asm("ex2.approx.f32 %0, %1;" : "=f"(y) : "f"(x));
    return y;
}

// ---------------------------------------------------------------------------
// prep_w: W[64][32000] * log2e -> fp16 rows [n][32 words]
// ---------------------------------------------------------------------------
__global__ __launch_bounds__(256) void prep_w_kernel(const float* __restrict__ w) {
    int n = blockIdx.x * 256 + threadIdx.x;
    uint32_t hi[32];
#pragma unroll
    for (int j = 0; j < 32; ++j) {
        float v0 = w[(2 * j) * D_OUT + n] * LOG2E;
        float v1 = w[(2 * j + 1) * D_OUT + n] * LOG2E;
        hi[j] = pack_h2(v0, v1);
    }
    uint4* d = reinterpret_cast<uint4*>(g_wprep) + (size_t)n * 8;
#pragma unroll
    for (int j = 0; j < 8; ++j)
        d[j] = make_uint4(hi[4*j], hi[4*j+1], hi[4*j+2], hi[4*j+3]);
}

// ---------------------------------------------------------------------------
// prep_x: x[8192][64] -> fp16 rows [r][32 words] of 1/x. 2 threads per row.
// ---------------------------------------------------------------------------
__global__ __launch_bounds__(256) void prep_x_kernel(const float* __restrict__ x) {
    int tid = blockIdx.x * 256 + threadIdx.x;
    int row = tid >> 1, half = tid & 1;
    const float4* xr = reinterpret_cast<const float4*>(&x[(size_t)row * D_IN + half * 32]);
    uint32_t hi[16];
#pragma unroll
    for (int j = 0; j < 8; ++j) {
        float4 v = xr[j];
        hi[2*j]   = pack_h2(1.0f / v.x, 1.0f / v.y);
        hi[2*j+1] = pack_h2(1.0f / v.z, 1.0f / v.w);
    }
    uint4* d = reinterpret_cast<uint4*>(g_xprep) + (size_t)row * 8 + half * 4;
#pragma unroll
    for (int j = 0; j < 4; ++j)
        d[j] = make_uint4(hi[4*j], hi[4*j+1], hi[4*j+2], hi[4*j+3]);
}

// ---------------------------------------------------------------------------
// Main HMMA pass. do_store=0: exp-sums into g_partials.
//                 do_store=1: out = 2^logit2 * rowinv.
// ---------------------------------------------------------------------------
__global__ __launch_bounds__(256)
void mma_pass_kernel(float* __restrict__ out, int do_store) {
    extern __shared__ uint32_t smem[];
    uint32_t* sA = smem;                 // [128][36]
    uint32_t* sB = smem + 128 * PITCH;   // [128][36]

    const int tid  = threadIdx.x;
    const int wid  = tid >> 5;
    const int lane = tid & 31;
    const int m0 = blockIdx.y * MT;
    const int n0 = blockIdx.x * NT;

    const uint32_t sA_a = smem_u32(sA);
    const uint32_t sB_a = smem_u32(sB);

    // ---- prologue: cp.async of prepped tiles (each 1024 uint4, 4/thread) ----
    {
        const uint4* gA = reinterpret_cast<const uint4*>(g_xprep + (size_t)m0 * 32);
        const uint4* gB = reinterpret_cast<const uint4*>(g_wprep + (size_t)n0 * 32);
#pragma unroll
        for (int j = 0; j < 4; ++j) {
            int f = tid + 256 * j;                               // 0..1023
            uint32_t doff = ((f >> 3) * PITCH + (f & 7) * 4) * 4;
            cpa16(sA_a + doff, gA + f);
            cpa16(sB_a + doff, gB + f);
        }
        asm volatile("cp.async.commit_group;" ::: "memory");
        asm volatile("cp.async.wait_group 0;" ::: "memory");
    }
    __syncthreads();

    // ---- fragment base addresses ----
    const int wm = wid & 3;
    const int wn = wid >> 2;
    const int g  = lane >> 2;
    const int t  = lane & 3;

    // A x4: {rows g k-lo, rows g+8 k-lo, rows g k-hi, rows g+8 k-hi}
    uint32_t aBase[2];
    {
        int arow = lane & 15;
        int ako  = (lane >> 4) * 16;
#pragma unroll
        for (int mi = 0; mi < 2; ++mi)
            aBase[mi] = sA_a + (uint32_t)(wm * 32 + mi * 16 + arow) * (PITCH * 4u) + ako;
    }
    // B x4 serves TWO n-tiles: {n0-7 k-lo, n0-7 k-hi, n8-15 k-lo, n8-15 k-hi}
    uint32_t bBase[4];
    {
        int brow  = (lane & 7) + ((lane >> 4) & 1) * 8;   // +8 rows for lanes 16-31
        int bko   = ((lane >> 3) & 1) * 16;               // k half for lanes 8-15,24-31
        uint32_t laneoff = (uint32_t)brow * (PITCH * 4u) + bko;
#pragma unroll
        for (int np = 0; np < 4; ++np)
            bBase[np] = sB_a + (uint32_t)(wn * 64 + np * 16) * (PITCH * 4u) + laneoff;
    }

    float acc[2][8][4];
#pragma unroll
    for (int mi = 0; mi < 2; ++mi)
#pragma unroll
        for (int ni = 0; ni < 8; ++ni)
#pragma unroll
            for (int c = 0; c < 4; ++c) acc[mi][ni][c] = 0.0f;

    // ---- mainloop: 4 k-chunks x (2 A-LDSM + 4 B-LDSM + 16 HMMA) ----
#pragma unroll
    for (int kc = 0; kc < 4; ++kc) {
        const uint32_t ko = kc * 32u;
        uint32_t ah[2][4];
#pragma unroll
        for (int mi = 0; mi < 2; ++mi)
            ldsm4(ah[mi], aBase[mi] + ko);
#pragma unroll
        for (int np = 0; np < 4; ++np) {
            uint32_t b[4];                 // {b0,b1} of ni=2np, {b0,b1} of ni=2np+1
            ldsm4(b, bBase[np] + ko);
#pragma unroll
            for (int mi = 0; mi < 2; ++mi) {
                mma_f16(acc[mi][2*np],     ah[mi], b[0], b[1]);
                mma_f16(acc[mi][2*np + 1], ah[mi], b[2], b[3]);
            }
        }
    }

    // ---- epilogue (logits are base-2) ----
#pragma unroll
    for (int mi = 0; mi < 2; ++mi) {
        const int rg = m0 + wm * 32 + mi * 16 + g;
        if (do_store) {
            const float inv0 = g_rowinv[rg];
            const float inv8 = g_rowinv[rg + 8];
            float* r0p = out + (size_t)rg * D_OUT + n0 + wn * 64 + t * 2;
            float* r8p = r0p + (size_t)8 * D_OUT;
#pragma unroll
            for (int ni = 0; ni < 8; ++ni) {
                float e0 = ex2(acc[mi][ni][0]);
                float e1 = ex2(acc[mi][ni][1]);
                float e2 = ex2(acc[mi][ni][2]);
                float e3 = ex2(acc[mi][ni][3]);
                __stcs(reinterpret_cast<float2*>(r0p + ni * 8), make_float2(e0 * inv0, e1 * inv0));
                __stcs(reinterpret_cast<float2*>(r8p + ni * 8), make_float2(e2 * inv8, e3 * inv8));
            }
        } else {
            float s0 = 0.0f, s8 = 0.0f;
#pragma unroll
            for (int ni = 0; ni < 8; ++ni) {
                s0 += ex2(acc[mi][ni][0]) + ex2(acc[mi][ni][1]);
                s8 += ex2(acc[mi][ni][2]) + ex2(acc[mi][ni][3]);
            }
            s0 += __shfl_xor_sync(0xffffffffu, s0, 1);
            s0 += __shfl_xor_sync(0xffffffffu, s0, 2);
            s8 += __shfl_xor_sync(0xffffffffu, s8, 1);
            s8 += __shfl_xor_sync(0xffffffffu, s8, 2);
            if (t == 0) {
                int pcol = blockIdx.x * 2 + wn;
                g_partials[(size_t)rg * NBLK2 + pcol]       = s0;
                g_partials[(size_t)(rg + 8) * NBLK2 + pcol] = s8;
            }
        }
    }
}

// ---------------------------------------------------------------------------
__global__ __launch_bounds__(256) void rowinv_kernel() {
    int warp = threadIdx.x >> 5;
    int lane = threadIdx.x & 31;
    int row = blockIdx.x * 8 + warp;
    float s = 0.0f;
    for (int i = lane; i < NBLK2; i += 32) s += g_partials[(size_t)row * NBLK2 + i];
#pragma unroll
    for (int off = 16; off >= 1; off >>= 1)
        s += __shfl_xor_sync(0xffffffffu, s, off);
    if (lane == 0) g_rowinv[row] = 1.0f / s;
}

__global__ void tail_kernel(float* __restrict__ out, long long base, long long n) {
    long long i = (long long)blockIdx.x * 256 + threadIdx.x;
    if (i < n) out[base + i] = 0.0f;
}

extern "C" void kernel_launch(void* const* d_in, const int* in_sizes, int n_in,
                              void* d_out, int out_size) {
    const float* x = (const float*)d_in[0];
    const float* w = (const float*)d_in[1];
    float* out = (float*)d_out;

    const int smem_bytes = 2 * 128 * PITCH * 4;   // 36864
    static int attr_set = 0;
    if (!attr_set) {
        cudaFuncSetAttribute(mma_pass_kernel,
                             cudaFuncAttributeMaxDynamicSharedMemorySize, smem_bytes);
        attr_set = 1;
    }

    prep_w_kernel<<<D_OUT / 256, 256>>>(w);
    prep_x_kernel<<<NROWS * 2 / 256, 256>>>(x);

    dim3 grid(NBLK, MBLK);   // (250, 64)
    mma_pass_kernel<<<grid, 256, smem_bytes>>>(out, 0);
    rowinv_kernel<<<NROWS / 8, 256>>>();
    mma_pass_kernel<<<grid, 256, smem_bytes>>>(out, 1);

    long long n_main = (long long)NROWS * D_OUT;
    long long tail = (long long)out_size - n_main;
    if (tail > 0) {
        int blocks = (int)((tail + 255) / 256);
        tail_kernel<<<blocks, 256>>>(out, n_main, tail);
    }
}